// round 1
// baseline (speedup 1.0000x reference)
#include <cuda_runtime.h>
#include <cuda_bf16.h>
#include <math.h>

// Problem constants
#define BB 8
#define TT 2048
#define DD 1024
#define HH 16
#define DH 64
#define DI 1024          // H*DH
#define MROWS (BB*TT)    // 16384

// ---------------- scratch (no cudaMalloc allowed) ----------------
__device__ float g_xn[(size_t)MROWS * DD];
__device__ float g_q [(size_t)MROWS * DI];
__device__ float g_k [(size_t)MROWS * DI];
__device__ float g_v [(size_t)MROWS * DI];
__device__ float g_a [(size_t)MROWS * DI];
__device__ float g_beta[(size_t)BB * HH * TT];
__device__ float g_o [(size_t)MROWS * DI];
__device__ float g_wbpad[1024 * 128];   // Wb padded to N=128 (pad stays zero from BSS)

__device__ __forceinline__ float sigmoidf_(float x) { return 1.f / (1.f + expf(-x)); }

// ---------------- LayerNorm: one block per row of 1024 ----------------
__global__ void __launch_bounds__(256) ln_kernel(const float* __restrict__ x,
                                                 const float* __restrict__ g,
                                                 const float* __restrict__ b,
                                                 float* __restrict__ xn)
{
    int row = blockIdx.x;
    int tid = threadIdx.x;
    const float4* xr = (const float4*)(x + (size_t)row * DD);
    float4 v = xr[tid];
    float s  = v.x + v.y + v.z + v.w;
    float ss = v.x * v.x + v.y * v.y + v.z * v.z + v.w * v.w;
    #pragma unroll
    for (int o = 16; o > 0; o >>= 1) {
        s  += __shfl_xor_sync(0xffffffffu, s,  o);
        ss += __shfl_xor_sync(0xffffffffu, ss, o);
    }
    __shared__ float shs[8], shss[8];
    if ((tid & 31) == 0) { shs[tid >> 5] = s; shss[tid >> 5] = ss; }
    __syncthreads();
    s = 0.f; ss = 0.f;
    #pragma unroll
    for (int w = 0; w < 8; w++) { s += shs[w]; ss += shss[w]; }
    float mu   = s * (1.f / 1024.f);
    float var  = ss * (1.f / 1024.f) - mu * mu;
    float rstd = rsqrtf(var + 1e-5f);
    float4 gv = ((const float4*)g)[tid];
    float4 bv = ((const float4*)b)[tid];
    float4 o4;
    o4.x = (v.x - mu) * rstd * gv.x + bv.x;
    o4.y = (v.y - mu) * rstd * gv.y + bv.y;
    o4.z = (v.z - mu) * rstd * gv.z + bv.z;
    o4.w = (v.w - mu) * rstd * gv.w + bv.w;
    ((float4*)(xn + (size_t)row * DD))[tid] = o4;
}

// ---------------- pack Wb (1024x16) into padded (1024x128) ----------------
__global__ void pack_wb_kernel(const float* __restrict__ Wb, float* __restrict__ wbp)
{
    int i = blockIdx.x * blockDim.x + threadIdx.x;   // 0..16383
    if (i < 1024 * 16) {
        int kk = i >> 4, n = i & 15;
        wbp[kk * 128 + n] = Wb[i];
    }
}

// ---------------- generic 128x128x8 SGEMM with epilogue modes ----------------
// mode 0: store to head layout [B,H,T,DH]
// mode 1: sigmoid(val + bias[n]) -> head layout
// mode 2: val + resid[m*N+n] -> row-major
// mode 3: (n<16) sigmoid(val + bias[n]) -> beta layout [B,H,T]
__global__ void __launch_bounds__(256) sgemm_kernel(
    const float* __restrict__ A, const float* __restrict__ B,
    float* __restrict__ C, const float* __restrict__ bias,
    const float* __restrict__ resid, int N, int K, int mode)
{
    __shared__ __align__(16) float As[8][128];
    __shared__ __align__(16) float Bs[8][128];
    int tid = threadIdx.x;
    int bx = blockIdx.x, by = blockIdx.y;

    int aRow = tid >> 1;
    int aCol = (tid & 1) << 2;
    int bRow = tid >> 5;
    int bCol = (tid & 31) << 2;

    const float* Ap = A + (size_t)(by * 128 + aRow) * K + aCol;
    const float* Bp = B + (size_t)bRow * N + bx * 128 + bCol;

    float acc[8][8];
    #pragma unroll
    for (int i = 0; i < 8; i++)
        #pragma unroll
        for (int j = 0; j < 8; j++) acc[i][j] = 0.f;

    int tx = (tid & 15) << 3;
    int ty = (tid >> 4) << 3;

    for (int k0 = 0; k0 < K; k0 += 8) {
        float4 av = *(const float4*)Ap;
        float4 bv = *(const float4*)Bp;
        Ap += 8;
        Bp += (size_t)8 * N;
        As[aCol + 0][aRow] = av.x;
        As[aCol + 1][aRow] = av.y;
        As[aCol + 2][aRow] = av.z;
        As[aCol + 3][aRow] = av.w;
        *(float4*)&Bs[bRow][bCol] = bv;
        __syncthreads();
        #pragma unroll
        for (int kk = 0; kk < 8; kk++) {
            float ar[8], br[8];
            *(float4*)(ar)     = *(const float4*)&As[kk][ty];
            *(float4*)(ar + 4) = *(const float4*)&As[kk][ty + 4];
            *(float4*)(br)     = *(const float4*)&Bs[kk][tx];
            *(float4*)(br + 4) = *(const float4*)&Bs[kk][tx + 4];
            #pragma unroll
            for (int i = 0; i < 8; i++)
                #pragma unroll
                for (int j = 0; j < 8; j++)
                    acc[i][j] = fmaf(ar[i], br[j], acc[i][j]);
        }
        __syncthreads();
    }

    int mbase = by * 128 + ty;
    int nbase = bx * 128 + tx;
    #pragma unroll
    for (int i = 0; i < 8; i++) {
        int m = mbase + i;
        int bidx = m >> 11;       // T = 2048
        int t    = m & 2047;
        #pragma unroll
        for (int j = 0; j < 8; j++) {
            int n = nbase + j;
            float val = acc[i][j];
            if (mode == 0) {
                int h = n >> 6, dh = n & 63;
                C[(((size_t)(bidx * HH + h)) * TT + t) * DH + dh] = val;
            } else if (mode == 1) {
                float sv = sigmoidf_(val + bias[n]);
                int h = n >> 6, dh = n & 63;
                C[(((size_t)(bidx * HH + h)) * TT + t) * DH + dh] = sv;
            } else if (mode == 2) {
                size_t idx = (size_t)m * N + n;
                C[idx] = val + resid[idx];
            } else { // mode 3
                if (n < 16) {
                    float sv = sigmoidf_(val + bias[n]);
                    C[((size_t)(bidx * HH + n)) * TT + t] = sv;
                }
            }
        }
    }
}

// ---------------- sequential SOKDA scan: 1 CTA per (b,h) chain ----------------
// Thread layout: 256 threads; r = tid>>2 (row 0..63), cb = tid&3 (16-col block).
// State: M[r][cb*16..] and ST[r][cb*16..] in registers (ST = S^T so all matvecs are row-dots).
__global__ void __launch_bounds__(256, 1) scan_kernel(
    const float* __restrict__ qg, const float* __restrict__ kg,
    const float* __restrict__ vg, const float* __restrict__ ag,
    const float* __restrict__ betag, const float* __restrict__ raw_gamma,
    float* __restrict__ og)
{
    int c = blockIdx.x;              // 0..127 chain id
    int bidx = c >> 4, h = c & 15;
    float gm = 1.f / (1.f + expf(-raw_gamma[h]));

    int tid  = threadIdx.x;
    int r    = tid >> 2;
    int cb   = tid & 3;
    int col0 = cb << 4;

    __shared__ __align__(16) float sh_k[64], sh_q[64], sh_v[64], sh_a[64], sh_mk[64];
    __shared__ float sh_red[8], sh_kn2[2], sh_beta[1];

    float Mreg[16], STreg[16];
    #pragma unroll
    for (int j = 0; j < 16; j++) { Mreg[j] = 0.f; STreg[j] = 0.f; }
    if ((r >> 4) == cb) Mreg[r & 15] = 1e-6f;   // M0 = EPS * I

    size_t chbase = (size_t)c * TT * DH;
    const float* qp = qg + chbase;
    const float* kp = kg + chbase;
    const float* vp = vg + chbase;
    const float* ap = ag + chbase;
    const float* bp = betag + (size_t)c * TT;
    float* op = og + (size_t)bidx * TT * DI + h * DH;

    // prefetch t = 0
    float pk = 0.f, pq = 0.f, pv = 0.f, pa = 0.f, pbeta = 0.f;
    if (tid < 64) { pk = kp[tid]; pq = qp[tid]; pv = vp[tid]; pa = ap[tid]; }
    if (tid == 64) pbeta = bp[0];

    for (int t = 0; t < TT; ++t) {
        // ---- phase 1: publish step inputs, partial ||k||^2, prefetch t+1 ----
        if (tid < 64) {
            sh_k[tid] = pk; sh_q[tid] = pq; sh_v[tid] = pv; sh_a[tid] = pa;
            float p = pk * pk;
            p += __shfl_xor_sync(0xffffffffu, p, 16);
            p += __shfl_xor_sync(0xffffffffu, p, 8);
            p += __shfl_xor_sync(0xffffffffu, p, 4);
            p += __shfl_xor_sync(0xffffffffu, p, 2);
            p += __shfl_xor_sync(0xffffffffu, p, 1);
            if ((tid & 31) == 0) sh_kn2[tid >> 5] = p;
        }
        if (tid == 64) sh_beta[0] = pbeta;
        if (t + 1 < TT) {
            int nb = (t + 1) * DH;
            if (tid < 64) { pk = kp[nb + tid]; pq = qp[nb + tid]; pv = vp[nb + tid]; pa = ap[nb + tid]; }
            if (tid == 64) pbeta = bp[t + 1];
        }
        __syncthreads();

        // ---- phase 2: M update + Mk (row dot) ----
        float n2   = sh_kn2[0] + sh_kn2[1];
        float invk = 1.f / fmaxf(sqrtf(n2), 1e-12f);
        float kc[16];
        #pragma unroll
        for (int jj = 0; jj < 16; jj += 4)
            *(float4*)(kc + jj) = *(const float4*)(sh_k + col0 + jj);
        float kr   = sh_k[r];
        float coef = invk * invk * kr;
        float mkp  = 0.f;
        #pragma unroll
        for (int j = 0; j < 16; j++) {
            Mreg[j] = fmaf(coef, kc[j], gm * Mreg[j]);
            mkp = fmaf(Mreg[j], kc[j], mkp);
        }
        mkp += __shfl_xor_sync(0xffffffffu, mkp, 1);
        mkp += __shfl_xor_sync(0xffffffffu, mkp, 2);
        float mk = mkp * invk;                    // Mk[r]
        if (cb == 0) sh_mk[r] = mk;
        float mval = (cb == 0) ? mk * mk : 0.f;   // ||Mk||^2 partials (8 rows per warp)
        mval += __shfl_xor_sync(0xffffffffu, mval, 16);
        mval += __shfl_xor_sync(0xffffffffu, mval, 8);
        mval += __shfl_xor_sync(0xffffffffu, mval, 4);
        mval += __shfl_xor_sync(0xffffffffu, mval, 2);
        mval += __shfl_xor_sync(0xffffffffu, mval, 1);
        if ((tid & 31) == 0) sh_red[tid >> 5] = mval;
        __syncthreads();

        // ---- phase 3: S update (fused alpha scale + two rank-1s) and output ----
        float mn2 = sh_red[0] + sh_red[1] + sh_red[2] + sh_red[3]
                  + sh_red[4] + sh_red[5] + sh_red[6] + sh_red[7];
        float invmk = 1.f / fmaxf(sqrtf(mn2), 1e-6f);
        float bet = sh_beta[0];
        float vr  = sh_v[r];
        float ac[16], mkc[16], qc[16];
        #pragma unroll
        for (int jj = 0; jj < 16; jj += 4) {
            *(float4*)(ac  + jj) = *(const float4*)(sh_a  + col0 + jj);
            *(float4*)(mkc + jj) = *(const float4*)(sh_mk + col0 + jj);
            *(float4*)(qc  + jj) = *(const float4*)(sh_q  + col0 + jj);
        }
        // kproj_e = invk * sum_d ST[e,d] * a[d] * k[d]   (on alpha-scaled S, per ref order)
        float p2 = 0.f;
        #pragma unroll
        for (int j = 0; j < 16; j++) p2 = fmaf(STreg[j], ac[j] * kc[j], p2);
        p2 += __shfl_xor_sync(0xffffffffu, p2, 1);
        p2 += __shfl_xor_sync(0xffffffffu, p2, 2);
        float bp2 = bet * invk * p2;    // b * kproj_e
        float bu  = bet * vr * invk;    // b * v_e, folded with kn = invk*k
        float bpm = bp2 * invmk;        // multiplies raw Mk to give b*kproj*k_tilde
        float po  = 0.f;
        #pragma unroll
        for (int j = 0; j < 16; j++) {
            float u = fmaf(bu, kc[j], -(bpm * mkc[j]));
            STreg[j] = fmaf(ac[j], STreg[j], u);
            po = fmaf(STreg[j], qc[j], po);
        }
        po += __shfl_xor_sync(0xffffffffu, po, 1);
        po += __shfl_xor_sync(0xffffffffu, po, 2);
        if (cb == 0) op[(size_t)t * DI + r] = po;
        __syncthreads();   // protect shared vectors before next phase-1 writes
    }
}

// ---------------- launch ----------------
extern "C" void kernel_launch(void* const* d_in, const int* in_sizes, int n_in,
                              void* d_out, int out_size)
{
    (void)in_sizes; (void)n_in; (void)out_size;
    const float* x    = (const float*)d_in[0];
    const float* ln_g = (const float*)d_in[1];
    const float* ln_b = (const float*)d_in[2];
    const float* Wq   = (const float*)d_in[3];
    const float* Wk   = (const float*)d_in[4];
    const float* Wv   = (const float*)d_in[5];
    const float* Wa   = (const float*)d_in[6];
    const float* ba   = (const float*)d_in[7];
    const float* Wb   = (const float*)d_in[8];
    const float* bb   = (const float*)d_in[9];
    const float* rg   = (const float*)d_in[10];
    const float* Wo   = (const float*)d_in[11];
    float* out = (float*)d_out;

    float *xn, *q_, *k_, *v_, *a_, *bet, *o_, *wbp;
    cudaGetSymbolAddress((void**)&xn,  g_xn);
    cudaGetSymbolAddress((void**)&q_,  g_q);
    cudaGetSymbolAddress((void**)&k_,  g_k);
    cudaGetSymbolAddress((void**)&v_,  g_v);
    cudaGetSymbolAddress((void**)&a_,  g_a);
    cudaGetSymbolAddress((void**)&bet, g_beta);
    cudaGetSymbolAddress((void**)&o_,  g_o);
    cudaGetSymbolAddress((void**)&wbp, g_wbpad);

    ln_kernel<<<MROWS, 256>>>(x, ln_g, ln_b, xn);
    pack_wb_kernel<<<16, 1024>>>(Wb, wbp);

    dim3 g1(DI / 128, MROWS / 128);   // (8, 128)
    sgemm_kernel<<<g1, 256>>>(xn, Wq, q_, nullptr, nullptr, DI, DD, 0);
    sgemm_kernel<<<g1, 256>>>(xn, Wk, k_, nullptr, nullptr, DI, DD, 0);
    sgemm_kernel<<<g1, 256>>>(xn, Wv, v_, nullptr, nullptr, DI, DD, 0);
    sgemm_kernel<<<g1, 256>>>(xn, Wa, a_, ba,      nullptr, DI, DD, 1);
    sgemm_kernel<<<dim3(1, MROWS / 128), 256>>>(xn, wbp, bet, bb, nullptr, 128, DD, 3);

    scan_kernel<<<BB * HH, 256>>>(q_, k_, v_, a_, bet, rg, o_);

    sgemm_kernel<<<g1, 256>>>(o_, Wo, out, nullptr, x, DD, DI, 2);
}

// round 2
// speedup vs baseline: 1.9166x; 1.9166x over previous
#include <cuda_runtime.h>
#include <cuda_bf16.h>
#include <math.h>

// Problem constants
#define BB 8
#define TT 2048
#define DD 1024
#define HH 16
#define DH 64
#define DI 1024          // H*DH
#define MROWS (BB*TT)    // 16384

// ---------------- scratch (no cudaMalloc allowed) ----------------
__device__ float g_xn[(size_t)MROWS * DD];
__device__ float g_q [(size_t)MROWS * DI];
__device__ float g_k [(size_t)MROWS * DI];
__device__ float g_v [(size_t)MROWS * DI];
__device__ float g_a [(size_t)MROWS * DI];
__device__ float g_beta[(size_t)BB * HH * TT];
__device__ float g_o [(size_t)MROWS * DI];
__device__ float g_wbpad[1024 * 128];   // Wb padded to N=128 (pad stays zero from BSS)

__device__ __forceinline__ float sigmoidf_(float x) { return 1.f / (1.f + expf(-x)); }

__device__ __forceinline__ float f2tf(float f) {
    unsigned u;
    asm("cvt.rna.tf32.f32 %0, %1;" : "=r"(u) : "f"(f));
    return __uint_as_float(u);
}

// ---------------- LayerNorm: one block per row of 1024 ----------------
__global__ void __launch_bounds__(256) ln_kernel(const float* __restrict__ x,
                                                 const float* __restrict__ g,
                                                 const float* __restrict__ b,
                                                 float* __restrict__ xn)
{
    int row = blockIdx.x;
    int tid = threadIdx.x;
    const float4* xr = (const float4*)(x + (size_t)row * DD);
    float4 v = xr[tid];
    float s  = v.x + v.y + v.z + v.w;
    float ss = v.x * v.x + v.y * v.y + v.z * v.z + v.w * v.w;
    #pragma unroll
    for (int o = 16; o > 0; o >>= 1) {
        s  += __shfl_xor_sync(0xffffffffu, s,  o);
        ss += __shfl_xor_sync(0xffffffffu, ss, o);
    }
    __shared__ float shs[8], shss[8];
    if ((tid & 31) == 0) { shs[tid >> 5] = s; shss[tid >> 5] = ss; }
    __syncthreads();
    s = 0.f; ss = 0.f;
    #pragma unroll
    for (int w = 0; w < 8; w++) { s += shs[w]; ss += shss[w]; }
    float mu   = s * (1.f / 1024.f);
    float var  = ss * (1.f / 1024.f) - mu * mu;
    float rstd = rsqrtf(var + 1e-5f);
    float4 gv = ((const float4*)g)[tid];
    float4 bv = ((const float4*)b)[tid];
    float4 o4;
    o4.x = (v.x - mu) * rstd * gv.x + bv.x;
    o4.y = (v.y - mu) * rstd * gv.y + bv.y;
    o4.z = (v.z - mu) * rstd * gv.z + bv.z;
    o4.w = (v.w - mu) * rstd * gv.w + bv.w;
    ((float4*)(xn + (size_t)row * DD))[tid] = o4;
}

// ---------------- pack Wb (1024x16) into padded (1024x128) ----------------
__global__ void pack_wb_kernel(const float* __restrict__ Wb, float* __restrict__ wbp)
{
    int i = blockIdx.x * blockDim.x + threadIdx.x;   // 0..16383
    if (i < 1024 * 16) {
        int kk = i >> 4, n = i & 15;
        wbp[kk * 128 + n] = Wb[i];
    }
}

// ---------------- TF32 tensor-core GEMM (mma.sync.m16n8k8) ----------------
// CTA tile 128x128, K-step 16, double-buffered smem, 8 warps (4 M x 2 N),
// each warp computes 32x64. Epilogue modes as before:
// mode 0: head layout [B,H,T,DH];  mode 1: sigmoid(+bias) -> head layout
// mode 2: +resid row-major;        mode 3: (n<16) sigmoid(+bias) -> [B,H,T]
__global__ void __launch_bounds__(256, 2) tf32gemm_kernel(
    const float* __restrict__ A, const float* __restrict__ B,
    float* __restrict__ C, const float* __restrict__ bias,
    const float* __restrict__ resid, int N, int K, int mode)
{
    __shared__ __align__(16) float As[2][128][20];   // [m][k], stride 20 -> conflict-free frag loads
    __shared__ __align__(16) float Bs[2][16][136];   // [k][n], stride 136 -> conflict-free frag loads

    const int tid  = threadIdx.x;
    const int lane = tid & 31, warp = tid >> 5;
    const int wm = warp >> 1, wn = warp & 1;
    const int gid = lane >> 2, tig = lane & 3;
    const int mbase = blockIdx.y * 128, nbase = blockIdx.x * 128;

    // gmem load mapping
    const int ar  = tid >> 2;          // A row 0..63 (s=1 adds 64)
    const int ac4 = (tid & 3) << 2;    // A col 0,4,8,12
    const int bk  = tid >> 5;          // B k-row 0..7 (s=1 adds 8)
    const int bn  = (tid & 31) << 2;   // B col group
    const float* Aptr = A + (size_t)(mbase + ar) * K + ac4;
    const float* Bptr = B + (size_t)bk * N + nbase + bn;

    float4 avr[2], bvr[2];
    avr[0] = *(const float4*)(Aptr);
    avr[1] = *(const float4*)(Aptr + (size_t)64 * K);
    bvr[0] = *(const float4*)(Bptr);
    bvr[1] = *(const float4*)(Bptr + (size_t)8 * N);
    Aptr += 16; Bptr += (size_t)16 * N;

    float c[2][8][4];
    #pragma unroll
    for (int mi = 0; mi < 2; mi++)
        #pragma unroll
        for (int nj = 0; nj < 8; nj++)
            #pragma unroll
            for (int e = 0; e < 4; e++) c[mi][nj][e] = 0.f;

    // stash tile 0 into buf 0
    #pragma unroll
    for (int s = 0; s < 2; s++) {
        float4 av = avr[s], bv = bvr[s], ta, tb;
        ta.x = f2tf(av.x); ta.y = f2tf(av.y); ta.z = f2tf(av.z); ta.w = f2tf(av.w);
        tb.x = f2tf(bv.x); tb.y = f2tf(bv.y); tb.z = f2tf(bv.z); tb.w = f2tf(bv.w);
        *(float4*)&As[0][ar + 64 * s][ac4] = ta;
        *(float4*)&Bs[0][bk + 8 * s][bn]   = tb;
    }
    __syncthreads();

    const int nk = K >> 4;
    for (int it = 0; it < nk; ++it) {
        const int buf = it & 1;
        const bool pf = (it + 1 < nk);
        if (pf) {
            avr[0] = *(const float4*)(Aptr);
            avr[1] = *(const float4*)(Aptr + (size_t)64 * K);
            bvr[0] = *(const float4*)(Bptr);
            bvr[1] = *(const float4*)(Bptr + (size_t)8 * N);
            Aptr += 16; Bptr += (size_t)16 * N;
        }
        #pragma unroll
        for (int ks = 0; ks < 2; ks++) {
            unsigned a[2][4], b[8][2];
            #pragma unroll
            for (int mi = 0; mi < 2; mi++) {
                const float* ap = &As[buf][wm * 32 + mi * 16 + gid][ks * 8 + tig];
                a[mi][0] = __float_as_uint(ap[0]);
                a[mi][1] = __float_as_uint(ap[8 * 20]);
                a[mi][2] = __float_as_uint(ap[4]);
                a[mi][3] = __float_as_uint(ap[8 * 20 + 4]);
            }
            #pragma unroll
            for (int nj = 0; nj < 8; nj++) {
                const float* bp = &Bs[buf][ks * 8 + tig][wn * 64 + nj * 8 + gid];
                b[nj][0] = __float_as_uint(bp[0]);
                b[nj][1] = __float_as_uint(bp[4 * 136]);
            }
            #pragma unroll
            for (int mi = 0; mi < 2; mi++)
                #pragma unroll
                for (int nj = 0; nj < 8; nj++)
                    asm volatile(
                        "mma.sync.aligned.m16n8k8.row.col.f32.tf32.tf32.f32 "
                        "{%0,%1,%2,%3}, {%4,%5,%6,%7}, {%8,%9}, {%0,%1,%2,%3};"
                        : "+f"(c[mi][nj][0]), "+f"(c[mi][nj][1]),
                          "+f"(c[mi][nj][2]), "+f"(c[mi][nj][3])
                        : "r"(a[mi][0]), "r"(a[mi][1]), "r"(a[mi][2]), "r"(a[mi][3]),
                          "r"(b[nj][0]), "r"(b[nj][1]));
        }
        if (pf) {
            const int nb = buf ^ 1;
            #pragma unroll
            for (int s = 0; s < 2; s++) {
                float4 av = avr[s], bv = bvr[s], ta, tb;
                ta.x = f2tf(av.x); ta.y = f2tf(av.y); ta.z = f2tf(av.z); ta.w = f2tf(av.w);
                tb.x = f2tf(bv.x); tb.y = f2tf(bv.y); tb.z = f2tf(bv.z); tb.w = f2tf(bv.w);
                *(float4*)&As[nb][ar + 64 * s][ac4] = ta;
                *(float4*)&Bs[nb][bk + 8 * s][bn]   = tb;
            }
        }
        __syncthreads();
    }

    // epilogue
    #pragma unroll
    for (int mi = 0; mi < 2; mi++) {
        #pragma unroll
        for (int half = 0; half < 2; half++) {
            int m = mbase + wm * 32 + mi * 16 + gid + half * 8;
            int bidx = m >> 11;        // T = 2048
            int t    = m & 2047;
            #pragma unroll
            for (int nj = 0; nj < 8; nj++) {
                int n = nbase + wn * 64 + nj * 8 + tig * 2;
                float v0 = c[mi][nj][half * 2 + 0];
                float v1 = c[mi][nj][half * 2 + 1];
                if (mode == 0) {
                    int h = n >> 6, dh = n & 63;
                    *(float2*)&C[(((size_t)(bidx * HH + h)) * TT + t) * DH + dh] =
                        make_float2(v0, v1);
                } else if (mode == 1) {
                    int h = n >> 6, dh = n & 63;
                    *(float2*)&C[(((size_t)(bidx * HH + h)) * TT + t) * DH + dh] =
                        make_float2(sigmoidf_(v0 + bias[n]), sigmoidf_(v1 + bias[n + 1]));
                } else if (mode == 2) {
                    size_t idx = (size_t)m * N + n;
                    float2 rr = *(const float2*)&resid[idx];
                    *(float2*)&C[idx] = make_float2(v0 + rr.x, v1 + rr.y);
                } else { // mode 3
                    if (n < 16) {
                        C[((size_t)(bidx * HH + n)) * TT + t]     = sigmoidf_(v0 + bias[n]);
                        C[((size_t)(bidx * HH + n + 1)) * TT + t] = sigmoidf_(v1 + bias[n + 1]);
                    }
                }
            }
        }
    }
}

// ---------------- sequential SOKDA scan: 1 CTA per (b,h) chain ----------------
// 256 threads; r = tid>>2 (row 0..63), cb = tid&3 (16-col block).
// State: M[r][cb*16..] and ST[r][cb*16..] in registers (ST = S^T -> all matvecs row-dots).
// 2 barriers per step (input vectors double-buffered).
__global__ void __launch_bounds__(256, 1) scan_kernel(
    const float* __restrict__ qg, const float* __restrict__ kg,
    const float* __restrict__ vg, const float* __restrict__ ag,
    const float* __restrict__ betag, const float* __restrict__ raw_gamma,
    float* __restrict__ og)
{
    int c = blockIdx.x;              // 0..127 chain id
    int bidx = c >> 4, h = c & 15;
    float gm = 1.f / (1.f + expf(-raw_gamma[h]));

    int tid  = threadIdx.x;
    int r    = tid >> 2;
    int cb   = tid & 3;
    int col0 = cb << 4;

    __shared__ __align__(16) float sh_k[2][64], sh_q[2][64], sh_v[2][64], sh_a[2][64];
    __shared__ __align__(16) float sh_mk[64];
    __shared__ float sh_red[8], sh_kn2[2], sh_beta[2];

    float Mreg[16], STreg[16];
    #pragma unroll
    for (int j = 0; j < 16; j++) { Mreg[j] = 0.f; STreg[j] = 0.f; }
    if ((r >> 4) == cb) Mreg[r & 15] = 1e-6f;   // M0 = EPS * I

    size_t chbase = (size_t)c * TT * DH;
    const float* qp = qg + chbase;
    const float* kp = kg + chbase;
    const float* vp = vg + chbase;
    const float* ap = ag + chbase;
    const float* bp = betag + (size_t)c * TT;
    float* op = og + (size_t)bidx * TT * DI + h * DH;

    // prefetch t = 0
    float pk = 0.f, pq = 0.f, pv = 0.f, pa = 0.f, pbeta = 0.f;
    if (tid < 64) { pk = kp[tid]; pq = qp[tid]; pv = vp[tid]; pa = ap[tid]; }
    if (tid == 64) pbeta = bp[0];

    for (int t = 0; t < TT; ++t) {
        const int buf = t & 1;
        // ---- phase 1: publish step inputs, partial ||k||^2, prefetch t+1 ----
        if (tid < 64) {
            sh_k[buf][tid] = pk; sh_q[buf][tid] = pq;
            sh_v[buf][tid] = pv; sh_a[buf][tid] = pa;
            float p = pk * pk;
            p += __shfl_xor_sync(0xffffffffu, p, 16);
            p += __shfl_xor_sync(0xffffffffu, p, 8);
            p += __shfl_xor_sync(0xffffffffu, p, 4);
            p += __shfl_xor_sync(0xffffffffu, p, 2);
            p += __shfl_xor_sync(0xffffffffu, p, 1);
            if ((tid & 31) == 0) sh_kn2[tid >> 5] = p;
        }
        if (tid == 64) sh_beta[buf] = pbeta;
        if (t + 1 < TT) {
            int nb = (t + 1) * DH;
            if (tid < 64) { pk = kp[nb + tid]; pq = qp[nb + tid]; pv = vp[nb + tid]; pa = ap[nb + tid]; }
            if (tid == 64) pbeta = bp[t + 1];
        }
        __syncthreads();   // A

        // ---- phase 2: M update + Mk (row dot) ----
        float n2   = sh_kn2[0] + sh_kn2[1];
        float invk = 1.f / fmaxf(sqrtf(n2), 1e-12f);
        float kc[16];
        #pragma unroll
        for (int jj = 0; jj < 16; jj += 4)
            *(float4*)(kc + jj) = *(const float4*)(&sh_k[buf][col0 + jj]);
        float kr   = sh_k[buf][r];
        float coef = invk * invk * kr;
        float mkp  = 0.f;
        #pragma unroll
        for (int j = 0; j < 16; j++) {
            Mreg[j] = fmaf(coef, kc[j], gm * Mreg[j]);
            mkp = fmaf(Mreg[j], kc[j], mkp);
        }
        mkp += __shfl_xor_sync(0xffffffffu, mkp, 1);
        mkp += __shfl_xor_sync(0xffffffffu, mkp, 2);
        float mk = mkp * invk;                    // Mk[r]
        if (cb == 0) sh_mk[r] = mk;
        float mval = (cb == 0) ? mk * mk : 0.f;   // ||Mk||^2 partials
        mval += __shfl_xor_sync(0xffffffffu, mval, 16);
        mval += __shfl_xor_sync(0xffffffffu, mval, 8);
        mval += __shfl_xor_sync(0xffffffffu, mval, 4);
        mval += __shfl_xor_sync(0xffffffffu, mval, 2);
        mval += __shfl_xor_sync(0xffffffffu, mval, 1);
        if ((tid & 31) == 0) sh_red[tid >> 5] = mval;
        __syncthreads();   // B

        // ---- phase 3: S update (fused alpha scale + two rank-1s) and output ----
        float mn2 = sh_red[0] + sh_red[1] + sh_red[2] + sh_red[3]
                  + sh_red[4] + sh_red[5] + sh_red[6] + sh_red[7];
        float invmk = 1.f / fmaxf(sqrtf(mn2), 1e-6f);
        float bet = sh_beta[buf];
        float vr  = sh_v[buf][r];
        float ac[16], mkc[16], qc[16];
        #pragma unroll
        for (int jj = 0; jj < 16; jj += 4) {
            *(float4*)(ac  + jj) = *(const float4*)(&sh_a[buf][col0 + jj]);
            *(float4*)(mkc + jj) = *(const float4*)(&sh_mk[col0 + jj]);
            *(float4*)(qc  + jj) = *(const float4*)(&sh_q[buf][col0 + jj]);
        }
        float p2 = 0.f;
        #pragma unroll
        for (int j = 0; j < 16; j++) p2 = fmaf(STreg[j], ac[j] * kc[j], p2);
        p2 += __shfl_xor_sync(0xffffffffu, p2, 1);
        p2 += __shfl_xor_sync(0xffffffffu, p2, 2);
        float bp2 = bet * invk * p2;    // b * kproj_e
        float bu  = bet * vr * invk;    // b * v_e (kn fold)
        float bpm = bp2 * invmk;        // scales raw Mk -> b*kproj*k_tilde
        float po  = 0.f;
        #pragma unroll
        for (int j = 0; j < 16; j++) {
            float u = fmaf(bu, kc[j], -(bpm * mkc[j]));
            STreg[j] = fmaf(ac[j], STreg[j], u);
            po = fmaf(STreg[j], qc[j], po);
        }
        po += __shfl_xor_sync(0xffffffffu, po, 1);
        po += __shfl_xor_sync(0xffffffffu, po, 2);
        if (cb == 0) op[(size_t)t * DI + r] = po;
        // no 3rd barrier: next-step P1 writes go to buf^1; sh_mk/sh_red
        // rewritten only after next barrier A.
    }
}

// ---------------- launch ----------------
extern "C" void kernel_launch(void* const* d_in, const int* in_sizes, int n_in,
                              void* d_out, int out_size)
{
    (void)in_sizes; (void)n_in; (void)out_size;
    const float* x    = (const float*)d_in[0];
    const float* ln_g = (const float*)d_in[1];
    const float* ln_b = (const float*)d_in[2];
    const float* Wq   = (const float*)d_in[3];
    const float* Wk   = (const float*)d_in[4];
    const float* Wv   = (const float*)d_in[5];
    const float* Wa   = (const float*)d_in[6];
    const float* ba   = (const float*)d_in[7];
    const float* Wb   = (const float*)d_in[8];
    const float* bb   = (const float*)d_in[9];
    const float* rg   = (const float*)d_in[10];
    const float* Wo   = (const float*)d_in[11];
    float* out = (float*)d_out;

    float *xn, *q_, *k_, *v_, *a_, *bet, *o_, *wbp;
    cudaGetSymbolAddress((void**)&xn,  g_xn);
    cudaGetSymbolAddress((void**)&q_,  g_q);
    cudaGetSymbolAddress((void**)&k_,  g_k);
    cudaGetSymbolAddress((void**)&v_,  g_v);
    cudaGetSymbolAddress((void**)&a_,  g_a);
    cudaGetSymbolAddress((void**)&bet, g_beta);
    cudaGetSymbolAddress((void**)&o_,  g_o);
    cudaGetSymbolAddress((void**)&wbp, g_wbpad);

    ln_kernel<<<MROWS, 256>>>(x, ln_g, ln_b, xn);
    pack_wb_kernel<<<16, 1024>>>(Wb, wbp);

    dim3 g1(DI / 128, MROWS / 128);   // (8, 128)
    tf32gemm_kernel<<<g1, 256>>>(xn, Wq, q_, nullptr, nullptr, DI, DD, 0);
    tf32gemm_kernel<<<g1, 256>>>(xn, Wk, k_, nullptr, nullptr, DI, DD, 0);
    tf32gemm_kernel<<<g1, 256>>>(xn, Wv, v_, nullptr, nullptr, DI, DD, 0);
    tf32gemm_kernel<<<g1, 256>>>(xn, Wa, a_, ba,      nullptr, DI, DD, 1);
    tf32gemm_kernel<<<dim3(1, MROWS / 128), 256>>>(xn, wbp, bet, bb, nullptr, 128, DD, 3);

    scan_kernel<<<BB * HH, 256>>>(q_, k_, v_, a_, bet, rg, o_);

    tf32gemm_kernel<<<g1, 256>>>(o_, Wo, out, nullptr, x, DD, DI, 2);
}

// round 3
// speedup vs baseline: 2.2651x; 1.1818x over previous
#include <cuda_runtime.h>
#include <cuda_bf16.h>
#include <math.h>

// Problem constants
#define BB 8
#define TT 2048
#define DD 1024
#define HH 16
#define DH 64
#define DI 1024          // H*DH
#define MROWS (BB*TT)    // 16384

// ---------------- scratch (no cudaMalloc allowed) ----------------
__device__ float g_xn[(size_t)MROWS * DD];
__device__ float g_q [(size_t)MROWS * DI];
__device__ float g_k [(size_t)MROWS * DI];
__device__ float g_v [(size_t)MROWS * DI];
__device__ float g_a [(size_t)MROWS * DI];
__device__ float g_beta[(size_t)BB * HH * TT];
__device__ float g_o [(size_t)MROWS * DI];
__device__ float g_wbpad[1024 * 128];   // Wb padded to N=128 (pad stays zero from BSS)

__device__ __forceinline__ float sigmoidf_(float x) { return 1.f / (1.f + expf(-x)); }

__device__ __forceinline__ float f2tf(float f) {
    unsigned u;
    asm("cvt.rna.tf32.f32 %0, %1;" : "=r"(u) : "f"(f));
    return __uint_as_float(u);
}

// ---------------- LayerNorm: one block per row of 1024 ----------------
__global__ void __launch_bounds__(256) ln_kernel(const float* __restrict__ x,
                                                 const float* __restrict__ g,
                                                 const float* __restrict__ b,
                                                 float* __restrict__ xn)
{
    int row = blockIdx.x;
    int tid = threadIdx.x;
    const float4* xr = (const float4*)(x + (size_t)row * DD);
    float4 v = xr[tid];
    float s  = v.x + v.y + v.z + v.w;
    float ss = v.x * v.x + v.y * v.y + v.z * v.z + v.w * v.w;
    #pragma unroll
    for (int o = 16; o > 0; o >>= 1) {
        s  += __shfl_xor_sync(0xffffffffu, s,  o);
        ss += __shfl_xor_sync(0xffffffffu, ss, o);
    }
    __shared__ float shs[8], shss[8];
    if ((tid & 31) == 0) { shs[tid >> 5] = s; shss[tid >> 5] = ss; }
    __syncthreads();
    s = 0.f; ss = 0.f;
    #pragma unroll
    for (int w = 0; w < 8; w++) { s += shs[w]; ss += shss[w]; }
    float mu   = s * (1.f / 1024.f);
    float var  = ss * (1.f / 1024.f) - mu * mu;
    float rstd = rsqrtf(var + 1e-5f);
    float4 gv = ((const float4*)g)[tid];
    float4 bv = ((const float4*)b)[tid];
    float4 o4;
    o4.x = (v.x - mu) * rstd * gv.x + bv.x;
    o4.y = (v.y - mu) * rstd * gv.y + bv.y;
    o4.z = (v.z - mu) * rstd * gv.z + bv.z;
    o4.w = (v.w - mu) * rstd * gv.w + bv.w;
    ((float4*)(xn + (size_t)row * DD))[tid] = o4;
}

// ---------------- pack Wb (1024x16) into padded (1024x128) ----------------
__global__ void pack_wb_kernel(const float* __restrict__ Wb, float* __restrict__ wbp)
{
    int i = blockIdx.x * blockDim.x + threadIdx.x;   // 0..16383
    if (i < 1024 * 16) {
        int kk = i >> 4, n = i & 15;
        wbp[kk * 128 + n] = Wb[i];
    }
}

// ---------------- TF32 tensor-core GEMM (mma.sync.m16n8k8) ----------------
// CTA tile 128x128, K-step 16, double-buffered smem, 4 warps (2M x 2N),
// each warp computes 64x64 (cuts smem fragment traffic 1.5x vs 8x(32x64)).
// Epilogue modes:
// mode 0: head layout [B,H,T,DH];  mode 1: sigmoid(+bias) -> head layout
// mode 2: +resid row-major;        mode 3: (n<16) sigmoid(+bias) -> [B,H,T]
__global__ void __launch_bounds__(128, 2) tf32gemm_kernel(
    const float* __restrict__ A, const float* __restrict__ B,
    float* __restrict__ C, const float* __restrict__ bias,
    const float* __restrict__ resid, int N, int K, int mode)
{
    __shared__ __align__(16) float As[2][128][20];   // [m][k], stride 20 -> conflict-free frag loads
    __shared__ __align__(16) float Bs[2][16][136];   // [k][n], stride 136 -> conflict-free frag loads

    const int tid  = threadIdx.x;
    const int lane = tid & 31, warp = tid >> 5;
    const int wm = warp >> 1, wn = warp & 1;
    const int gid = lane >> 2, tig = lane & 3;
    const int mbase = blockIdx.y * 128, nbase = blockIdx.x * 128;

    // gmem load mapping (128 threads, 4 row-passes each)
    const int ar  = tid >> 2;          // A row 0..31 (+32*s)
    const int ac4 = (tid & 3) << 2;    // A col 0,4,8,12
    const int bk  = tid >> 5;          // B k-row 0..3 (+4*s)
    const int bn  = (tid & 31) << 2;   // B col group
    const float* Aptr = A + (size_t)(mbase + ar) * K + ac4;
    const float* Bptr = B + (size_t)bk * N + nbase + bn;

    float4 avr[4], bvr[4];
    #pragma unroll
    for (int s = 0; s < 4; s++) {
        avr[s] = *(const float4*)(Aptr + (size_t)(32 * s) * K);
        bvr[s] = *(const float4*)(Bptr + (size_t)(4 * s) * N);
    }
    Aptr += 16; Bptr += (size_t)16 * N;

    float c[4][8][4];
    #pragma unroll
    for (int mi = 0; mi < 4; mi++)
        #pragma unroll
        for (int nj = 0; nj < 8; nj++)
            #pragma unroll
            for (int e = 0; e < 4; e++) c[mi][nj][e] = 0.f;

    // stash tile 0 into buf 0
    #pragma unroll
    for (int s = 0; s < 4; s++) {
        float4 av = avr[s], bv = bvr[s], ta, tb;
        ta.x = f2tf(av.x); ta.y = f2tf(av.y); ta.z = f2tf(av.z); ta.w = f2tf(av.w);
        tb.x = f2tf(bv.x); tb.y = f2tf(bv.y); tb.z = f2tf(bv.z); tb.w = f2tf(bv.w);
        *(float4*)&As[0][ar + 32 * s][ac4] = ta;
        *(float4*)&Bs[0][bk + 4 * s][bn]   = tb;
    }
    __syncthreads();

    const int nk = K >> 4;
    for (int it = 0; it < nk; ++it) {
        const int buf = it & 1;
        const bool pf = (it + 1 < nk);
        if (pf) {
            #pragma unroll
            for (int s = 0; s < 4; s++) {
                avr[s] = *(const float4*)(Aptr + (size_t)(32 * s) * K);
                bvr[s] = *(const float4*)(Bptr + (size_t)(4 * s) * N);
            }
            Aptr += 16; Bptr += (size_t)16 * N;
        }
        #pragma unroll
        for (int ks = 0; ks < 2; ks++) {
            unsigned a[4][4], b[8][2];
            #pragma unroll
            for (int mi = 0; mi < 4; mi++) {
                const float* ap = &As[buf][wm * 64 + mi * 16 + gid][ks * 8 + tig];
                a[mi][0] = __float_as_uint(ap[0]);
                a[mi][1] = __float_as_uint(ap[8 * 20]);
                a[mi][2] = __float_as_uint(ap[4]);
                a[mi][3] = __float_as_uint(ap[8 * 20 + 4]);
            }
            #pragma unroll
            for (int nj = 0; nj < 8; nj++) {
                const float* bp = &Bs[buf][ks * 8 + tig][wn * 64 + nj * 8 + gid];
                b[nj][0] = __float_as_uint(bp[0]);
                b[nj][1] = __float_as_uint(bp[4 * 136]);
            }
            #pragma unroll
            for (int mi = 0; mi < 4; mi++)
                #pragma unroll
                for (int nj = 0; nj < 8; nj++)
                    asm volatile(
                        "mma.sync.aligned.m16n8k8.row.col.f32.tf32.tf32.f32 "
                        "{%0,%1,%2,%3}, {%4,%5,%6,%7}, {%8,%9}, {%0,%1,%2,%3};"
                        : "+f"(c[mi][nj][0]), "+f"(c[mi][nj][1]),
                          "+f"(c[mi][nj][2]), "+f"(c[mi][nj][3])
                        : "r"(a[mi][0]), "r"(a[mi][1]), "r"(a[mi][2]), "r"(a[mi][3]),
                          "r"(b[nj][0]), "r"(b[nj][1]));
        }
        if (pf) {
            const int nb = buf ^ 1;
            #pragma unroll
            for (int s = 0; s < 4; s++) {
                float4 av = avr[s], bv = bvr[s], ta, tb;
                ta.x = f2tf(av.x); ta.y = f2tf(av.y); ta.z = f2tf(av.z); ta.w = f2tf(av.w);
                tb.x = f2tf(bv.x); tb.y = f2tf(bv.y); tb.z = f2tf(bv.z); tb.w = f2tf(bv.w);
                *(float4*)&As[nb][ar + 32 * s][ac4] = ta;
                *(float4*)&Bs[nb][bk + 4 * s][bn]   = tb;
            }
        }
        __syncthreads();
    }

    // epilogue
    #pragma unroll
    for (int mi = 0; mi < 4; mi++) {
        #pragma unroll
        for (int half = 0; half < 2; half++) {
            int m = mbase + wm * 64 + mi * 16 + gid + half * 8;
            int bidx = m >> 11;        // T = 2048
            int t    = m & 2047;
            #pragma unroll
            for (int nj = 0; nj < 8; nj++) {
                int n = nbase + wn * 64 + nj * 8 + tig * 2;
                float v0 = c[mi][nj][half * 2 + 0];
                float v1 = c[mi][nj][half * 2 + 1];
                if (mode == 0) {
                    int h = n >> 6, dh = n & 63;
                    *(float2*)&C[(((size_t)(bidx * HH + h)) * TT + t) * DH + dh] =
                        make_float2(v0, v1);
                } else if (mode == 1) {
                    int h = n >> 6, dh = n & 63;
                    *(float2*)&C[(((size_t)(bidx * HH + h)) * TT + t) * DH + dh] =
                        make_float2(sigmoidf_(v0 + bias[n]), sigmoidf_(v1 + bias[n + 1]));
                } else if (mode == 2) {
                    size_t idx = (size_t)m * N + n;
                    float2 rr = *(const float2*)&resid[idx];
                    *(float2*)&C[idx] = make_float2(v0 + rr.x, v1 + rr.y);
                } else { // mode 3
                    if (n < 16) {
                        C[((size_t)(bidx * HH + n)) * TT + t]     = sigmoidf_(v0 + bias[n]);
                        C[((size_t)(bidx * HH + n + 1)) * TT + t] = sigmoidf_(v1 + bias[n + 1]);
                    }
                }
            }
        }
    }
}

// ---------------- sequential SOKDA scan: 1 CTA per (b,h) chain ----------------
// 256 threads; r = tid>>2 (row 0..63), cb = tid&3 (16-col block).
// ONE barrier per step: inputs triple-buffered (published one step ahead in P2),
// mk/red double-buffered. ||k||^2 computed redundantly per thread (no reduction
// round-trip). rsqrt instead of sqrt+div. Split accumulators in all dots.
__global__ void __launch_bounds__(256, 1) scan_kernel(
    const float* __restrict__ qg, const float* __restrict__ kg,
    const float* __restrict__ vg, const float* __restrict__ ag,
    const float* __restrict__ betag, const float* __restrict__ raw_gamma,
    float* __restrict__ og)
{
    int c = blockIdx.x;              // 0..127 chain id
    int bidx = c >> 4, h = c & 15;
    float gm = 1.f / (1.f + expf(-raw_gamma[h]));

    int tid  = threadIdx.x;
    int r    = tid >> 2;
    int cb   = tid & 3;
    int col0 = cb << 4;

    __shared__ __align__(16) float sh_k[3][64], sh_q[3][64], sh_v[3][64], sh_a[3][64];
    __shared__ __align__(16) float sh_mk[2][64];
    __shared__ float sh_red[2][8], sh_beta[3];

    float Mreg[16], STreg[16];
    #pragma unroll
    for (int j = 0; j < 16; j++) { Mreg[j] = 0.f; STreg[j] = 0.f; }
    if ((r >> 4) == cb) Mreg[r & 15] = 1e-6f;   // M0 = EPS * I

    size_t chbase = (size_t)c * TT * DH;
    const float* qp = qg + chbase;
    const float* kp = kg + chbase;
    const float* vp = vg + chbase;
    const float* ap = ag + chbase;
    const float* bp = betag + (size_t)c * TT;
    float* op = og + (size_t)bidx * TT * DI + h * DH;

    // preamble: publish t=0 to slot 0, prefetch t=1 into regs
    float pk = 0.f, pq = 0.f, pv = 0.f, pa = 0.f, pbeta = 0.f;
    if (tid < 64) {
        sh_k[0][tid] = kp[tid]; sh_q[0][tid] = qp[tid];
        sh_v[0][tid] = vp[tid]; sh_a[0][tid] = ap[tid];
        pk = kp[DH + tid]; pq = qp[DH + tid];
        pv = vp[DH + tid]; pa = ap[DH + tid];
    }
    if (tid == 64) { sh_beta[0] = bp[0]; pbeta = bp[1]; }
    __syncthreads();

    int slot = 0, nslot = 1, aslot = 2;
    for (int t = 0; t < TT; ++t) {
        const int mslot = t & 1;

        // ---- P2a: publish inputs for t+1, prefetch t+2 ----
        if (t + 1 < TT) {
            if (tid < 64) {
                sh_k[nslot][tid] = pk; sh_q[nslot][tid] = pq;
                sh_v[nslot][tid] = pv; sh_a[nslot][tid] = pa;
            }
            if (tid == 64) sh_beta[nslot] = pbeta;
        }
        if (t + 2 < TT) {
            int nb = (t + 2) * DH;
            if (tid < 64) {
                pk = kp[nb + tid]; pq = qp[nb + tid];
                pv = vp[nb + tid]; pa = ap[nb + tid];
            }
            if (tid == 64) pbeta = bp[t + 2];
        }

        // ---- P2b: ||k||^2 (redundant), M update + Mk ----
        float kc[16];
        #pragma unroll
        for (int jj = 0; jj < 16; jj += 4)
            *(float4*)(kc + jj) = *(const float4*)(&sh_k[slot][col0 + jj]);
        float kr = sh_k[slot][r];

        float s0 = 0.f, s1 = 0.f, s2 = 0.f, s3 = 0.f;
        #pragma unroll
        for (int j = 0; j < 16; j += 4) {
            s0 = fmaf(kc[j],     kc[j],     s0);
            s1 = fmaf(kc[j + 1], kc[j + 1], s1);
            s2 = fmaf(kc[j + 2], kc[j + 2], s2);
            s3 = fmaf(kc[j + 3], kc[j + 3], s3);
        }
        float n2 = (s0 + s1) + (s2 + s3);
        n2 += __shfl_xor_sync(0xffffffffu, n2, 1);
        n2 += __shfl_xor_sync(0xffffffffu, n2, 2);
        float invk = rsqrtf(fmaxf(n2, 1e-24f));
        float coef = invk * invk * kr;

        float d0 = 0.f, d1 = 0.f, d2 = 0.f, d3 = 0.f;
        #pragma unroll
        for (int j = 0; j < 16; j += 4) {
            Mreg[j]     = fmaf(coef, kc[j],     gm * Mreg[j]);
            Mreg[j + 1] = fmaf(coef, kc[j + 1], gm * Mreg[j + 1]);
            Mreg[j + 2] = fmaf(coef, kc[j + 2], gm * Mreg[j + 2]);
            Mreg[j + 3] = fmaf(coef, kc[j + 3], gm * Mreg[j + 3]);
            d0 = fmaf(Mreg[j],     kc[j],     d0);
            d1 = fmaf(Mreg[j + 1], kc[j + 1], d1);
            d2 = fmaf(Mreg[j + 2], kc[j + 2], d2);
            d3 = fmaf(Mreg[j + 3], kc[j + 3], d3);
        }
        float mkp = (d0 + d1) + (d2 + d3);
        mkp += __shfl_xor_sync(0xffffffffu, mkp, 1);
        mkp += __shfl_xor_sync(0xffffffffu, mkp, 2);
        float mk = mkp * invk;                    // Mk[r]
        if (cb == 0) sh_mk[mslot][r] = mk;
        float mval = (cb == 0) ? mk * mk : 0.f;
        mval += __shfl_xor_sync(0xffffffffu, mval, 4);
        mval += __shfl_xor_sync(0xffffffffu, mval, 8);
        mval += __shfl_xor_sync(0xffffffffu, mval, 16);
        if ((tid & 31) == 0) sh_red[mslot][tid >> 5] = mval;
        __syncthreads();

        // ---- P3: S update + output ----
        float mn2 = ((sh_red[mslot][0] + sh_red[mslot][1]) + (sh_red[mslot][2] + sh_red[mslot][3]))
                  + ((sh_red[mslot][4] + sh_red[mslot][5]) + (sh_red[mslot][6] + sh_red[mslot][7]));
        float invmk = rsqrtf(fmaxf(mn2, 1e-12f));
        float bet = sh_beta[slot];
        float vr  = sh_v[slot][r];
        float ac[16], mkc[16], qc[16];
        #pragma unroll
        for (int jj = 0; jj < 16; jj += 4) {
            *(float4*)(ac  + jj) = *(const float4*)(&sh_a[slot][col0 + jj]);
            *(float4*)(mkc + jj) = *(const float4*)(&sh_mk[mslot][col0 + jj]);
            *(float4*)(qc  + jj) = *(const float4*)(&sh_q[slot][col0 + jj]);
        }
        float e0 = 0.f, e1 = 0.f, e2 = 0.f, e3 = 0.f;
        #pragma unroll
        for (int j = 0; j < 16; j += 4) {
            e0 = fmaf(STreg[j],     ac[j]     * kc[j],     e0);
            e1 = fmaf(STreg[j + 1], ac[j + 1] * kc[j + 1], e1);
            e2 = fmaf(STreg[j + 2], ac[j + 2] * kc[j + 2], e2);
            e3 = fmaf(STreg[j + 3], ac[j + 3] * kc[j + 3], e3);
        }
        float p2 = (e0 + e1) + (e2 + e3);
        p2 += __shfl_xor_sync(0xffffffffu, p2, 1);
        p2 += __shfl_xor_sync(0xffffffffu, p2, 2);
        float bp2 = bet * invk * p2;    // b * kproj_e
        float bu  = bet * vr * invk;    // b * v_e (kn fold)
        float bpm = bp2 * invmk;        // scales raw Mk -> b*kproj*k_tilde
        float o0 = 0.f, o1 = 0.f, o2 = 0.f, o3 = 0.f;
        #pragma unroll
        for (int j = 0; j < 16; j += 4) {
            float u0 = fmaf(bu, kc[j],     -(bpm * mkc[j]));
            float u1 = fmaf(bu, kc[j + 1], -(bpm * mkc[j + 1]));
            float u2 = fmaf(bu, kc[j + 2], -(bpm * mkc[j + 2]));
            float u3 = fmaf(bu, kc[j + 3], -(bpm * mkc[j + 3]));
            STreg[j]     = fmaf(ac[j],     STreg[j],     u0);
            STreg[j + 1] = fmaf(ac[j + 1], STreg[j + 1], u1);
            STreg[j + 2] = fmaf(ac[j + 2], STreg[j + 2], u2);
            STreg[j + 3] = fmaf(ac[j + 3], STreg[j + 3], u3);
            o0 = fmaf(STreg[j],     qc[j],     o0);
            o1 = fmaf(STreg[j + 1], qc[j + 1], o1);
            o2 = fmaf(STreg[j + 2], qc[j + 2], o2);
            o3 = fmaf(STreg[j + 3], qc[j + 3], o3);
        }
        float po = (o0 + o1) + (o2 + o3);
        po += __shfl_xor_sync(0xffffffffu, po, 1);
        po += __shfl_xor_sync(0xffffffffu, po, 2);
        if (cb == 0) op[(size_t)t * DI + r] = po;

        // rotate input slots
        int tmp = slot; slot = nslot; nslot = aslot; aslot = tmp;
        // NO second barrier: next step's P2 writes go to rotated slots / other
        // mslot; reads of this step's slots were ordered by this barrier.
    }
}

// ---------------- launch ----------------
extern "C" void kernel_launch(void* const* d_in, const int* in_sizes, int n_in,
                              void* d_out, int out_size)
{
    (void)in_sizes; (void)n_in; (void)out_size;
    const float* x    = (const float*)d_in[0];
    const float* ln_g = (const float*)d_in[1];
    const float* ln_b = (const float*)d_in[2];
    const float* Wq   = (const float*)d_in[3];
    const float* Wk   = (const float*)d_in[4];
    const float* Wv   = (const float*)d_in[5];
    const float* Wa   = (const float*)d_in[6];
    const float* ba   = (const float*)d_in[7];
    const float* Wb   = (const float*)d_in[8];
    const float* bb   = (const float*)d_in[9];
    const float* rg   = (const float*)d_in[10];
    const float* Wo   = (const float*)d_in[11];
    float* out = (float*)d_out;

    float *xn, *q_, *k_, *v_, *a_, *bet, *o_, *wbp;
    cudaGetSymbolAddress((void**)&xn,  g_xn);
    cudaGetSymbolAddress((void**)&q_,  g_q);
    cudaGetSymbolAddress((void**)&k_,  g_k);
    cudaGetSymbolAddress((void**)&v_,  g_v);
    cudaGetSymbolAddress((void**)&a_,  g_a);
    cudaGetSymbolAddress((void**)&bet, g_beta);
    cudaGetSymbolAddress((void**)&o_,  g_o);
    cudaGetSymbolAddress((void**)&wbp, g_wbpad);

    ln_kernel<<<MROWS, 256>>>(x, ln_g, ln_b, xn);
    pack_wb_kernel<<<16, 1024>>>(Wb, wbp);

    dim3 g1(DI / 128, MROWS / 128);   // (8, 128)
    tf32gemm_kernel<<<g1, 128>>>(xn, Wq, q_, nullptr, nullptr, DI, DD, 0);
    tf32gemm_kernel<<<g1, 128>>>(xn, Wk, k_, nullptr, nullptr, DI, DD, 0);
    tf32gemm_kernel<<<g1, 128>>>(xn, Wv, v_, nullptr, nullptr, DI, DD, 0);
    tf32gemm_kernel<<<g1, 128>>>(xn, Wa, a_, ba,      nullptr, DI, DD, 1);
    tf32gemm_kernel<<<dim3(1, MROWS / 128), 128>>>(xn, wbp, bet, bb, nullptr, 128, DD, 3);

    scan_kernel<<<BB * HH, 256>>>(q_, k_, v_, a_, bet, rg, o_);

    tf32gemm_kernel<<<g1, 128>>>(o_, Wo, out, nullptr, x, DD, DI, 2);
}